// round 16
// baseline (speedup 1.0000x reference)
#include <cuda_runtime.h>
#include <cuda_bf16.h>
#include <stdint.h>
#include <math.h>

// ---------------------------------------------------------------------------
// Problem constants: b=4, c=128, a=25, h=w=32
// Token order: m = ba*1024 + p (ba-major). Conv K order: k = tap*128 + c.
// ---------------------------------------------------------------------------
#define TOK_M   102400
#define D_MOD   256
#define D_FF    512
#define QKV_N   768
#define BA      100
#define PIX     1024
#define CCH     128
#define AA      25
#define KIN     1152

// ------------------------- scratch (static device) -------------------------
__device__ float g_T  [TOK_M * D_MOD];
__device__ float g_PE [TOK_M * D_MOD];
__device__ float g_QKV[TOK_M * QKV_N];
__device__ float g_S2 [TOK_M * D_MOD];

__device__ __nv_bfloat16 gA_hi[(size_t)TOK_M * KIN];
__device__ __nv_bfloat16 gA_lo[(size_t)TOK_M * KIN];
__device__ __nv_bfloat16 gX_hi[TOK_M * D_MOD],  gX_lo[TOK_M * D_MOD];
__device__ __nv_bfloat16 gAO_hi[TOK_M * D_MOD], gAO_lo[TOK_M * D_MOD];
__device__ __nv_bfloat16 gY_hi[TOK_M * D_MOD],  gY_lo[TOK_M * D_MOD];
__device__ __nv_bfloat16 gF_hi[TOK_M * D_FF],   gF_lo[TOK_M * D_FF];

__device__ __nv_bfloat16 gWmlp_hi [D_MOD * KIN],   gWmlp_lo [D_MOD * KIN];
__device__ __nv_bfloat16 gWqkv_hi [QKV_N * D_MOD], gWqkv_lo [QKV_N * D_MOD];
__device__ __nv_bfloat16 gWproj_hi[D_MOD * D_MOD], gWproj_lo[D_MOD * D_MOD];
__device__ __nv_bfloat16 gW1_hi   [D_FF * D_MOD],  gW1_lo   [D_FF * D_MOD];
__device__ __nv_bfloat16 gW2_hi   [D_MOD * D_FF],  gW2_lo   [D_MOD * D_FF];
__device__ __nv_bfloat16 gWc_hi   [CCH * D_MOD],   gWc_lo   [CCH * D_MOD];

// ---------------------------------------------------------------------------
// base-target-legal PTX helpers (sm_80+)
// ---------------------------------------------------------------------------
__device__ __forceinline__ uint32_t smem_u32(const void* p) {
    uint32_t a;
    asm("{ .reg .u64 t; cvta.to.shared.u64 t, %1; cvt.u32.u64 %0, t; }"
        : "=r"(a) : "l"(p));
    return a;
}
__device__ __forceinline__ void ldsm_x4(uint32_t* r, uint32_t addr) {
    asm volatile("ldmatrix.sync.aligned.m8n8.x4.shared.b16 {%0,%1,%2,%3}, [%4];"
        : "=r"(r[0]), "=r"(r[1]), "=r"(r[2]), "=r"(r[3]) : "r"(addr));
}
__device__ __forceinline__ void mma16816(float* c, const uint32_t* a, const uint32_t* b) {
    asm volatile(
        "mma.sync.aligned.m16n8k16.row.col.f32.bf16.bf16.f32 "
        "{%0,%1,%2,%3}, {%4,%5,%6,%7}, {%8,%9}, {%0,%1,%2,%3};"
        : "+f"(c[0]), "+f"(c[1]), "+f"(c[2]), "+f"(c[3])
        : "r"(a[0]), "r"(a[1]), "r"(a[2]), "r"(a[3]), "r"(b[0]), "r"(b[1]));
}
#define CP16(dst, src) \
    asm volatile("cp.async.cg.shared.global [%0], [%1], 16;" \
        :: "r"(dst), "l"(src) : "memory")
#define CP_COMMIT() asm volatile("cp.async.commit_group;" ::: "memory")
#define CP_WAIT0()  asm volatile("cp.async.wait_group 0;" ::: "memory")
#define CP_WAIT1()  asm volatile("cp.async.wait_group 1;" ::: "memory")

// pack 8 floats -> 8 bf16 (hi) and 8 residual bf16 (lo) as uint4 each
__device__ __forceinline__ void pack8(const float* v, uint4& hq, uint4& lq) {
    __nv_bfloat162 hp[4], lp[4];
#pragma unroll
    for (int i = 0; i < 4; i++) {
        __nv_bfloat16 h0 = __float2bfloat16_rn(v[2*i]);
        __nv_bfloat16 h1 = __float2bfloat16_rn(v[2*i+1]);
        hp[i].x = h0; hp[i].y = h1;
        lp[i].x = __float2bfloat16_rn(v[2*i]   - __bfloat162float(h0));
        lp[i].y = __float2bfloat16_rn(v[2*i+1] - __bfloat162float(h1));
    }
    hq = *(uint4*)hp;
    lq = *(uint4*)lp;
}

// ---------------------------------------------------------------------------
// bf16x3 HMMA GEMM (round-11 validated). BM=128, BN=128, BK=32; 512 threads,
// 16 warps (4m x 4n), warp tile 32x32. 3-stage cp.async, 1 sync/chunk.
// ---------------------------------------------------------------------------
#define RS 40
#define SM_AH 0
#define SM_AL 10240
#define SM_BH 20480
#define SM_BL 30720
#define SM_BUF 40960
#define GSM_TOTAL (3 * SM_BUF)   // 122880

__global__ __launch_bounds__(512) void gemm_mma(
    const __nv_bfloat16* __restrict__ Ahi, const __nv_bfloat16* __restrict__ Alo,
    const __nv_bfloat16* __restrict__ Bhi, const __nv_bfloat16* __restrict__ Blo,
    float* __restrict__ C, int M, int N, int K,
    const float* __restrict__ bias, const float* __restrict__ resid, int relu,
    __nv_bfloat16* __restrict__ Ohi, __nv_bfloat16* __restrict__ Olo,
    float* __restrict__ sai)
{
    extern __shared__ char sm[];
    const uint32_t smb = smem_u32(sm);
    const int tid = threadIdx.x;
    const int lane = tid & 31;
    const int wid = tid >> 5;
    const int warpm = wid & 3;
    const int warpn = wid >> 2;
    const int m0 = blockIdx.y * 128;
    const int n0 = blockIdx.x * 128;

    const int row = tid >> 2;
    const int seg = tid & 3;
    const uint32_t ld_sm_off = (uint32_t)row * (RS * 2) + seg * 16;
    const __nv_bfloat16* pAh = Ahi + (size_t)(m0 + row) * K + seg * 8;
    const __nv_bfloat16* pAl = Alo + (size_t)(m0 + row) * K + seg * 8;
    const __nv_bfloat16* pBh = Bhi + (size_t)(n0 + row) * K + seg * 8;
    const __nv_bfloat16* pBl = Blo + (size_t)(n0 + row) * K + seg * 8;

    const int nch = K >> 5;

#pragma unroll
    for (int pt = 0; pt < 2; pt++) {
        const uint32_t stg = (uint32_t)pt * SM_BUF;
        const size_t kc = (size_t)pt * 32;
        CP16(smb + stg + SM_AH + ld_sm_off, pAh + kc);
        CP16(smb + stg + SM_AL + ld_sm_off, pAl + kc);
        CP16(smb + stg + SM_BH + ld_sm_off, pBh + kc);
        CP16(smb + stg + SM_BL + ld_sm_off, pBl + kc);
        CP_COMMIT();
    }

    float acc[2][4][4];
#pragma unroll
    for (int im = 0; im < 2; im++)
#pragma unroll
        for (int in = 0; in < 4; in++)
#pragma unroll
            for (int r = 0; r < 4; r++) acc[im][in][r] = 0.f;

    const uint32_t a_ld_row = (uint32_t)(warpm * 32 + (lane & 15));
    const uint32_t a_ld_k8  = (uint32_t)((lane >> 4) * 8);
    const uint32_t b_ld_row = (uint32_t)(warpn * 32 + ((lane >> 4) & 1) * 8 + (lane & 7));
    const uint32_t b_ld_k8  = (uint32_t)(((lane >> 3) & 1) * 8);

    int sc = 0;
    for (int t = 0; t < nch; t++) {
        if (t + 1 < nch) { CP_WAIT1(); } else { CP_WAIT0(); }
        __syncthreads();

        if (t + 2 < nch) {
            const int si = (sc >= 1) ? sc - 1 : 2;
            const uint32_t stg = (uint32_t)si * SM_BUF;
            const size_t kc = (size_t)(t + 2) * 32;
            CP16(smb + stg + SM_AH + ld_sm_off, pAh + kc);
            CP16(smb + stg + SM_AL + ld_sm_off, pAl + kc);
            CP16(smb + stg + SM_BH + ld_sm_off, pBh + kc);
            CP16(smb + stg + SM_BL + ld_sm_off, pBl + kc);
            CP_COMMIT();
        }

        const uint32_t cur = (uint32_t)sc * SM_BUF;
#pragma unroll
        for (int ks = 0; ks < 2; ks++) {
            uint32_t ah[2][4], al[2][4], bh[4][2], bl[4][2];
#pragma unroll
            for (int im = 0; im < 2; im++) {
                const uint32_t ao = cur +
                    ((a_ld_row + im * 16) * RS + ks * 16 + a_ld_k8) * 2;
                ldsm_x4(ah[im], smb + SM_AH + ao);
                ldsm_x4(al[im], smb + SM_AL + ao);
            }
#pragma unroll
            for (int p = 0; p < 2; p++) {
                const uint32_t bo = cur +
                    ((b_ld_row + p * 16) * RS + ks * 16 + b_ld_k8) * 2;
                uint32_t r[4];
                ldsm_x4(r, smb + SM_BH + bo);
                bh[2*p][0] = r[0]; bh[2*p][1] = r[1];
                bh[2*p+1][0] = r[2]; bh[2*p+1][1] = r[3];
                ldsm_x4(r, smb + SM_BL + bo);
                bl[2*p][0] = r[0]; bl[2*p][1] = r[1];
                bl[2*p+1][0] = r[2]; bl[2*p+1][1] = r[3];
            }
#pragma unroll
            for (int im = 0; im < 2; im++)
#pragma unroll
                for (int in = 0; in < 4; in++) {
                    mma16816(acc[im][in], ah[im], bh[in]);
                    mma16816(acc[im][in], ah[im], bl[in]);
                    mma16816(acc[im][in], al[im], bh[in]);
                }
        }
        sc = (sc >= 2) ? 0 : sc + 1;
    }

    // ---- epilogue ----
#pragma unroll
    for (int im = 0; im < 2; im++) {
#pragma unroll
        for (int in = 0; in < 4; in++) {
            const int mrow = m0 + warpm * 32 + im * 16 + (lane >> 2);
            const int ncol = n0 + warpn * 32 + in * 8 + (lane & 3) * 2;
#pragma unroll
            for (int r = 0; r < 2; r++) {
                const int m = mrow + r * 8;
                float v0 = acc[im][in][r * 2 + 0];
                float v1 = acc[im][in][r * 2 + 1];
                if (bias)  { v0 += bias[ncol]; v1 += bias[ncol + 1]; }
                if (relu)  { v0 = fmaxf(v0, 0.f); v1 = fmaxf(v1, 0.f); }
                if (resid) {
                    const float* rp = resid + (size_t)m * N + ncol;
                    v0 += rp[0]; v1 += rp[1];
                }
                if (C) {
                    float2 f2; f2.x = v0; f2.y = v1;
                    *(float2*)(C + (size_t)m * N + ncol) = f2;
                }
                if (Ohi) {
                    __nv_bfloat16 h0 = __float2bfloat16_rn(v0);
                    __nv_bfloat16 h1 = __float2bfloat16_rn(v1);
                    __nv_bfloat162 hv; hv.x = h0; hv.y = h1;
                    __nv_bfloat162 lv;
                    lv.x = __float2bfloat16_rn(v0 - __bfloat162float(h0));
                    lv.y = __float2bfloat16_rn(v1 - __bfloat162float(h1));
                    *(__nv_bfloat162*)(Ohi + (size_t)m * N + ncol) = hv;
                    *(__nv_bfloat162*)(Olo + (size_t)m * N + ncol) = lv;
                }
                if (sai) {
                    const int ba = m >> 10, p = m & 1023;
                    const int b_ = ba / AA, a_ = ba - b_ * AA;
                    sai[((size_t)(b_ * CCH + ncol)     * AA + a_) * PIX + p] = v0;
                    sai[((size_t)(b_ * CCH + ncol + 1) * AA + a_) * PIX + p] = v1;
                }
            }
        }
    }
}

// ---------------------------------------------------------------------------
// weight transpose + split kernels
// ---------------------------------------------------------------------------
__global__ void wsplit_kernel(const float* __restrict__ W, int K, int N,
                              __nv_bfloat16* __restrict__ oh,
                              __nv_bfloat16* __restrict__ ol)
{
    const int idx = blockIdx.x * 256 + threadIdx.x;
    if (idx >= K * N) return;
    const int k = idx / N, n = idx - k * N;
    const float v = W[idx];
    const __nv_bfloat16 h = __float2bfloat16_rn(v);
    oh[(size_t)n * K + k] = h;
    ol[(size_t)n * K + k] = __float2bfloat16_rn(v - __bfloat162float(h));
}

__global__ void wsplit_mlp(const float* __restrict__ W,
                           __nv_bfloat16* __restrict__ oh,
                           __nv_bfloat16* __restrict__ ol)
{
    const int idx = blockIdx.x * 256 + threadIdx.x;
    if (idx >= KIN * D_MOD) return;
    const int kk = idx / D_MOD, n = idx - kk * D_MOD;
    const int c = kk / 9, tap = kk - c * 9;
    const int kp = tap * 128 + c;
    const float v = W[idx];
    const __nv_bfloat16 h = __float2bfloat16_rn(v);
    oh[(size_t)n * KIN + kp] = h;
    ol[(size_t)n * KIN + kp] = __float2bfloat16_rn(v - __bfloat162float(h));
}

// vectorized elementwise split: 8 elems/thread, uint4 packed outputs
__global__ void split_kernel(const float* __restrict__ X, size_t n,
                             __nv_bfloat16* __restrict__ oh,
                             __nv_bfloat16* __restrict__ ol)
{
    const size_t i = ((size_t)blockIdx.x * 256 + threadIdx.x) * 8;
    if (i >= n) return;
    float v[8];
    *(float4*)(v)     = *(const float4*)(X + i);
    *(float4*)(v + 4) = *(const float4*)(X + i + 4);
    uint4 hq, lq;
    pack8(v, hq, lq);
    *(uint4*)(oh + i) = hq;
    *(uint4*)(ol + i) = lq;
}

// ---------------------------------------------------------------------------
// im2col (coalesced, round-14 validated): A[m = ba*1024+p][k = tap*128+c].
// ---------------------------------------------------------------------------
__global__ __launch_bounds__(256) void im2col2(
    const float* __restrict__ src,
    __nv_bfloat16* __restrict__ Ahi, __nv_bfloat16* __restrict__ Alo)
{
    __shared__ float xs[32 * 321];
    const int tid = threadIdx.x;
    const int i0 = blockIdx.x * 8;
    const int c0 = blockIdx.y * 32;
    const int ba = blockIdx.z;
    const int b_ = ba / AA, a_ = ba - b_ * AA;

    for (int l = tid; l < 10240; l += 256) {
        const int c = l / 320;
        const int rem = l - c * 320;
        const int r = rem >> 5, col = rem & 31;
        const int ii = i0 - 1 + r;
        float v = 0.f;
        if (ii >= 0 && ii < 32)
            v = src[(((size_t)(b_ * CCH + c0 + c)) * AA + a_) * PIX + ii * 32 + col];
        xs[c * 321 + rem] = v;
    }
    __syncthreads();

    const int w = tid >> 5, lane = tid & 31;
    const int i = i0 + w;
    const float* xrow = xs + lane * 321;
    for (int j = 0; j < 32; j++) {
        const size_t m = (size_t)ba * PIX + i * 32 + j;
        const size_t mbase = m * KIN + c0 + lane;
#pragma unroll
        for (int tap = 0; tap < 9; tap++) {
            const int di = tap / 3, dj = tap - di * 3 - 1;
            const int jj = j + dj;
            float v = 0.f;
            if (jj >= 0 && jj < 32) v = xrow[(w + di) * 32 + jj];
            const __nv_bfloat16 h = __float2bfloat16_rn(v);
            Ahi[mbase + (size_t)tap * 128] = h;
            Alo[mbase + (size_t)tap * 128] =
                __float2bfloat16_rn(v - __bfloat162float(h));
        }
    }
}

// ---------------------------------------------------------------------------
// LayerNorm v2: warp-per-row (8 rows/CTA), float4 loads, uint4 packed stores.
// ---------------------------------------------------------------------------
__global__ __launch_bounds__(256) void ln_kernel(
    const float* __restrict__ X, const float* __restrict__ addsrc,
    const float* __restrict__ g, const float* __restrict__ b,
    __nv_bfloat16* __restrict__ oh, __nv_bfloat16* __restrict__ ol)
{
    const int w = threadIdx.x >> 5, lane = threadIdx.x & 31;
    const size_t row = (size_t)blockIdx.x * 8 + w;
    const size_t base = row * D_MOD + lane * 8;

    float v[8];
    *(float4*)(v)     = *(const float4*)(X + base);
    *(float4*)(v + 4) = *(const float4*)(X + base + 4);
    if (addsrc) {
        float a[8];
        *(float4*)(a)     = *(const float4*)(addsrc + base);
        *(float4*)(a + 4) = *(const float4*)(addsrc + base + 4);
#pragma unroll
        for (int i = 0; i < 8; i++) v[i] += a[i];
    }

    float s = 0.f;
#pragma unroll
    for (int i = 0; i < 8; i++) s += v[i];
#pragma unroll
    for (int o = 16; o; o >>= 1) s += __shfl_xor_sync(0xffffffffu, s, o);
    const float mean = s * (1.f / 256.f);

    float q = 0.f;
#pragma unroll
    for (int i = 0; i < 8; i++) {
        v[i] -= mean;
        q += v[i] * v[i];
    }
#pragma unroll
    for (int o = 16; o; o >>= 1) q += __shfl_xor_sync(0xffffffffu, q, o);
    const float rstd = rsqrtf(q * (1.f / 256.f) + 1e-5f);

    float gv[8], bv[8];
    *(float4*)(gv)     = *(const float4*)(g + lane * 8);
    *(float4*)(gv + 4) = *(const float4*)(g + lane * 8 + 4);
    *(float4*)(bv)     = *(const float4*)(b + lane * 8);
    *(float4*)(bv + 4) = *(const float4*)(b + lane * 8 + 4);

    float r[8];
#pragma unroll
    for (int i = 0; i < 8; i++) r[i] = v[i] * rstd * gv[i] + bv[i];

    uint4 hq, lq;
    pack8(r, hq, lq);
    *(uint4*)(oh + base) = hq;
    *(uint4*)(ol + base) = lq;
}

// ---------------------------------------------------------------------------
// Fused attention v3 — 4-query batching (validated round 11).
// ---------------------------------------------------------------------------
#define KTP 101
#define TAILPAD 64
#define ATT_SMEM_FLOATS (256 * KTP + 25600 + 3200 + 3200 + TAILPAD)
#define ATT_SMEM_BYTES  (ATT_SMEM_FLOATS * 4)

__global__ __launch_bounds__(256) void attn_kernel(
    const float* __restrict__ qkv,
    __nv_bfloat16* __restrict__ outh, __nv_bfloat16* __restrict__ outl,
    const float* __restrict__ Wl, const float* __restrict__ bl,
    const float* __restrict__ Ww, const float* __restrict__ bw,
    const float* __restrict__ lamb)
{
    extern __shared__ float smf[];
    float* Kt   = smf;
    float* Vs   = Kt + 256 * KTP;
    float* sraw = Vs + 25600;
    float* satt = sraw + 3200;

    const int tid = threadIdx.x;
    const int g = tid >> 5, lane = tid & 31;
    const int bq = blockIdx.x;
    const float scale = 0.17677669529663687f;

    float wl[8], ww[8];
#pragma unroll
    for (int h = 0; h < 8; h++) { wl[h] = Wl[g * 8 + h]; ww[h] = Ww[g * 8 + h]; }
    const float blg = bl[g], bwg = bw[g];
    const float lam = 1.f + lamb[g];

    for (int idx = tid; idx < 25600; idx += 256) {
        const int m = idx >> 8, cc = idx & 255;
        const size_t rowb = ((size_t)m * PIX + bq) * QKV_N;
        Kt[cc * KTP + m] = qkv[rowb + 256 + cc];
        Vs[idx]          = qkv[rowb + 512 + cc];
    }
    __syncthreads();

    for (int n = 0; n < BA; n += 4) {
        float qr[4];
#pragma unroll
        for (int q = 0; q < 4; q++)
            qr[q] = qkv[((size_t)(n + q) * PIX + bq) * QKV_N + tid] * scale;

        float a[4][4];
#pragma unroll
        for (int q = 0; q < 4; q++)
#pragma unroll
            for (int r = 0; r < 4; r++) a[q][r] = 0.f;
        const float* kb = Kt + (g * 32) * KTP;
#pragma unroll
        for (int dd = 0; dd < 32; dd++) {
            float qd[4];
#pragma unroll
            for (int q = 0; q < 4; q++)
                qd[q] = __shfl_sync(0xffffffffu, qr[q], dd);
            const float* kr = kb + dd * KTP;
            const float k0 = kr[lane];
            const float k1 = kr[32 + lane];
            const float k2 = kr[64 + lane];
            const float k3 = kr[96 + lane];
#pragma unroll
            for (int q = 0; q < 4; q++) {
                a[q][0] += qd[q] * k0;
                a[q][1] += qd[q] * k1;
                a[q][2] += qd[q] * k2;
                a[q][3] += qd[q] * k3;
            }
        }
#pragma unroll
        for (int q = 0; q < 4; q++) {
            float* srq = sraw + q * 800 + g * 100;
            srq[lane]      = a[q][0];
            srq[32 + lane] = a[q][1];
            srq[64 + lane] = a[q][2];
            if (lane < 4) srq[96 + lane] = a[q][3];
        }
        __syncthreads();

#pragma unroll
        for (int q = 0; q < 4; q++) {
            float s0 = blg, s1 = blg, s2 = blg, s3 = blg;
#pragma unroll
            for (int h = 0; h < 8; h++) {
                const float* sr = sraw + q * 800 + h * 100;
                const float w = wl[h];
                s0 += w * sr[lane];
                s1 += w * sr[32 + lane];
                s2 += w * sr[64 + lane];
                s3 += w * sr[96 + lane];
            }
            if (lane >= 4) s3 = -1e30f;
            float mx = fmaxf(fmaxf(s0, s1), fmaxf(s2, s3));
#pragma unroll
            for (int o = 16; o; o >>= 1) mx = fmaxf(mx, __shfl_xor_sync(0xffffffffu, mx, o));
            float e0 = __expf(s0 - mx);
            float e1 = __expf(s1 - mx);
            float e2 = __expf(s2 - mx);
            float e3 = (lane < 4) ? __expf(s3 - mx) : 0.f;
            float sum = e0 + e1 + e2 + e3;
#pragma unroll
            for (int o = 16; o; o >>= 1) sum += __shfl_xor_sync(0xffffffffu, sum, o);
            const float inv = 1.f / sum;
            float* saq = satt + q * 800 + g * 100;
            saq[lane]      = e0 * inv;
            saq[32 + lane] = e1 * inv;
            saq[64 + lane] = e2 * inv;
            if (lane < 4) saq[96 + lane] = e3 * inv;
        }
        __syncthreads();

        float w4[4][4];
#pragma unroll
        for (int q = 0; q < 4; q++) {
            float w0 = bwg, w1 = bwg, w2 = bwg, w3 = bwg;
#pragma unroll
            for (int h = 0; h < 8; h++) {
                const float* sa = satt + q * 800 + h * 100;
                const float w = ww[h];
                w0 += w * sa[lane];
                w1 += w * sa[32 + lane];
                w2 += w * sa[64 + lane];
                w3 += w * sa[96 + lane];
            }
            w4[q][0] = 0.01f + (w0 - 0.01f) * lam;
            w4[q][1] = 0.01f + (w1 - 0.01f) * lam;
            w4[q][2] = 0.01f + (w2 - 0.01f) * lam;
            w4[q][3] = 0.01f + (w3 - 0.01f) * lam;
        }

        float o4[4] = {0.f, 0.f, 0.f, 0.f};
        const float* vb = Vs + g * 32 + lane;
#pragma unroll 4
        for (int sl = 0; sl < 32; sl++) {
            const float v0 = vb[sl * 256];
            const float v1 = vb[(32 + sl) * 256];
            const float v2 = vb[(64 + sl) * 256];
#pragma unroll
            for (int q = 0; q < 4; q++) {
                o4[q] += __shfl_sync(0xffffffffu, w4[q][0], sl) * v0;
                o4[q] += __shfl_sync(0xffffffffu, w4[q][1], sl) * v1;
                o4[q] += __shfl_sync(0xffffffffu, w4[q][2], sl) * v2;
            }
        }
#pragma unroll
        for (int sl = 0; sl < 4; sl++) {
            const float v3 = vb[(96 + sl) * 256];
#pragma unroll
            for (int q = 0; q < 4; q++)
                o4[q] += __shfl_sync(0xffffffffu, w4[q][3], sl) * v3;
        }
#pragma unroll
        for (int q = 0; q < 4; q++) {
            const size_t oi = ((size_t)(n + q) * PIX + bq) * D_MOD + g * 32 + lane;
            const __nv_bfloat16 h = __float2bfloat16_rn(o4[q]);
            outh[oi] = h;
            outl[oi] = __float2bfloat16_rn(o4[q] - __bfloat162float(h));
        }
    }
}

// ---------------------------------------------------------------------------
extern "C" void kernel_launch(void* const* d_in, const int* in_sizes, int n_in,
                              void* d_out, int out_size)
{
    const float* buffer  = (const float*)d_in[0];
    const float* spa_pos = (const float*)d_in[1];
    const float* W_mlp   = (const float*)d_in[2];
    const float* g1      = (const float*)d_in[3];
    const float* b1      = (const float*)d_in[4];
    const float* Wqkv    = (const float*)d_in[5];
    const float* Wproj   = (const float*)d_in[6];
    const float* bproj   = (const float*)d_in[7];
    const float* Wl      = (const float*)d_in[8];
    const float* bl      = (const float*)d_in[9];
    const float* Ww      = (const float*)d_in[10];
    const float* bw      = (const float*)d_in[11];
    const float* lamb    = (const float*)d_in[12];
    const float* g2      = (const float*)d_in[13];
    const float* b2      = (const float*)d_in[14];
    const float* W1      = (const float*)d_in[15];
    const float* W2      = (const float*)d_in[16];
    const float* Wconv   = (const float*)d_in[17];
    float* out = (float*)d_out;

    float *T, *PE, *QKV, *S2;
    cudaGetSymbolAddress((void**)&T,   g_T);
    cudaGetSymbolAddress((void**)&PE,  g_PE);
    cudaGetSymbolAddress((void**)&QKV, g_QKV);
    cudaGetSymbolAddress((void**)&S2,  g_S2);

    __nv_bfloat16 *Ah, *Al, *Xh, *Xl, *AOh, *AOl, *Yh, *Yl, *Fh, *Fl;
    __nv_bfloat16 *Wmh, *Wml, *Wqh, *Wql, *Wph, *Wpl, *W1h, *W1l, *W2h, *W2l, *Wch, *Wcl;
    cudaGetSymbolAddress((void**)&Ah,  gA_hi);   cudaGetSymbolAddress((void**)&Al,  gA_lo);
    cudaGetSymbolAddress((void**)&Xh,  gX_hi);   cudaGetSymbolAddress((void**)&Xl,  gX_lo);
    cudaGetSymbolAddress((void**)&AOh, gAO_hi);  cudaGetSymbolAddress((void**)&AOl, gAO_lo);
    cudaGetSymbolAddress((void**)&Yh,  gY_hi);   cudaGetSymbolAddress((void**)&Yl,  gY_lo);
    cudaGetSymbolAddress((void**)&Fh,  gF_hi);   cudaGetSymbolAddress((void**)&Fl,  gF_lo);
    cudaGetSymbolAddress((void**)&Wmh, gWmlp_hi);  cudaGetSymbolAddress((void**)&Wml, gWmlp_lo);
    cudaGetSymbolAddress((void**)&Wqh, gWqkv_hi);  cudaGetSymbolAddress((void**)&Wql, gWqkv_lo);
    cudaGetSymbolAddress((void**)&Wph, gWproj_hi); cudaGetSymbolAddress((void**)&Wpl, gWproj_lo);
    cudaGetSymbolAddress((void**)&W1h, gW1_hi);    cudaGetSymbolAddress((void**)&W1l, gW1_lo);
    cudaGetSymbolAddress((void**)&W2h, gW2_hi);    cudaGetSymbolAddress((void**)&W2l, gW2_lo);
    cudaGetSymbolAddress((void**)&Wch, gWc_hi);    cudaGetSymbolAddress((void**)&Wcl, gWc_lo);

    cudaFuncSetAttribute(attn_kernel, cudaFuncAttributeMaxDynamicSharedMemorySize,
                         ATT_SMEM_BYTES);
    cudaFuncSetAttribute(gemm_mma, cudaFuncAttributeMaxDynamicSharedMemorySize,
                         GSM_TOTAL);

    // App launch #4 = ncu capture target (conv GEMM).
    im2col2<<<dim3(4, 4, BA), 256>>>(buffer, Ah, Al);
    wsplit_mlp<<<(KIN * D_MOD + 255) / 256, 256>>>(W_mlp, Wmh, Wml);
    wsplit_kernel<<<(D_MOD * QKV_N + 255) / 256, 256>>>(Wqkv, D_MOD, QKV_N, Wqh, Wql);
    gemm_mma<<<dim3(D_MOD / 128, TOK_M / 128), 512, GSM_TOTAL>>>(
        Ah, Al, Wmh, Wml, T, TOK_M, D_MOD, KIN,
        nullptr, nullptr, 0, nullptr, nullptr, nullptr);
    im2col2<<<dim3(4, 4, BA), 256>>>(spa_pos, Ah, Al);
    gemm_mma<<<dim3(D_MOD / 128, TOK_M / 128), 512, GSM_TOTAL>>>(
        Ah, Al, Wmh, Wml, PE, TOK_M, D_MOD, KIN,
        nullptr, nullptr, 0, nullptr, nullptr, nullptr);
    wsplit_kernel<<<(D_MOD * D_MOD + 255) / 256, 256>>>(Wproj, D_MOD, D_MOD, Wph, Wpl);
    wsplit_kernel<<<(D_MOD * D_FF + 255) / 256, 256>>>(W1, D_MOD, D_FF, W1h, W1l);
    wsplit_kernel<<<(D_FF * D_MOD + 255) / 256, 256>>>(W2, D_FF, D_MOD, W2h, W2l);
    split_kernel<<<(CCH * D_MOD / 8 + 255) / 256, 256>>>(
        Wconv, (size_t)CCH * D_MOD, Wch, Wcl);

    ln_kernel<<<TOK_M / 8, 256>>>(T, PE, g1, b1, Xh, Xl);

    gemm_mma<<<dim3(QKV_N / 128, TOK_M / 128), 512, GSM_TOTAL>>>(
        Xh, Xl, Wqh, Wql, QKV, TOK_M, QKV_N, D_MOD,
        nullptr, nullptr, 0, nullptr, nullptr, nullptr);

    attn_kernel<<<PIX, 256, ATT_SMEM_BYTES>>>(QKV, AOh, AOl, Wl, bl, Ww, bw, lamb);

    gemm_mma<<<dim3(D_MOD / 128, TOK_M / 128), 512, GSM_TOTAL>>>(
        AOh, AOl, Wph, Wpl, S2, TOK_M, D_MOD, D_MOD,
        bproj, T, 0, nullptr, nullptr, nullptr);

    ln_kernel<<<TOK_M / 8, 256>>>(S2, nullptr, g2, b2, Yh, Yl);

    gemm_mma<<<dim3(D_FF / 128, TOK_M / 128), 512, GSM_TOTAL>>>(
        Yh, Yl, W1h, W1l, nullptr, TOK_M, D_FF, D_MOD,
        nullptr, nullptr, 1, Fh, Fl, nullptr);
    gemm_mma<<<dim3(D_MOD / 128, TOK_M / 128), 512, GSM_TOTAL>>>(
        Fh, Fl, W2h, W2l, nullptr, TOK_M, D_MOD, D_FF,
        nullptr, S2, 0, Xh, Xl, nullptr);

    gemm_mma<<<dim3(CCH / 128, TOK_M / 128), 512, GSM_TOTAL>>>(
        Xh, Xl, Wch, Wcl, nullptr, TOK_M, CCH, D_MOD,
        nullptr, nullptr, 0, nullptr, nullptr, out);
}

// round 17
// speedup vs baseline: 1.5304x; 1.5304x over previous
#include <cuda_runtime.h>
#include <cuda_bf16.h>
#include <stdint.h>
#include <math.h>

// ---------------------------------------------------------------------------
// Problem constants: b=4, c=128, a=25, h=w=32
// Token order: m = ba*1024 + p (ba-major). Conv K order: k = tap*128 + c.
// ---------------------------------------------------------------------------
#define TOK_M   102400
#define D_MOD   256
#define D_FF    512
#define QKV_N   768
#define BA      100
#define PIX     1024
#define CCH     128
#define AA      25
#define KIN     1152

// ------------------------- scratch (static device) -------------------------
__device__ float g_T  [TOK_M * D_MOD];
__device__ float g_PE [TOK_M * D_MOD];
__device__ float g_QKV[TOK_M * QKV_N];
__device__ float g_S2 [TOK_M * D_MOD];

__device__ __nv_bfloat16 gA_hi[(size_t)TOK_M * KIN];
__device__ __nv_bfloat16 gA_lo[(size_t)TOK_M * KIN];
__device__ __nv_bfloat16 gX_hi[TOK_M * D_MOD],  gX_lo[TOK_M * D_MOD];
__device__ __nv_bfloat16 gAO_hi[TOK_M * D_MOD], gAO_lo[TOK_M * D_MOD];
__device__ __nv_bfloat16 gY_hi[TOK_M * D_MOD],  gY_lo[TOK_M * D_MOD];
__device__ __nv_bfloat16 gF_hi[TOK_M * D_FF],   gF_lo[TOK_M * D_FF];

__device__ __nv_bfloat16 gWmlp_hi [D_MOD * KIN],   gWmlp_lo [D_MOD * KIN];
__device__ __nv_bfloat16 gWqkv_hi [QKV_N * D_MOD], gWqkv_lo [QKV_N * D_MOD];
__device__ __nv_bfloat16 gWproj_hi[D_MOD * D_MOD], gWproj_lo[D_MOD * D_MOD];
__device__ __nv_bfloat16 gW1_hi   [D_FF * D_MOD],  gW1_lo   [D_FF * D_MOD];
__device__ __nv_bfloat16 gW2_hi   [D_MOD * D_FF],  gW2_lo   [D_MOD * D_FF];
__device__ __nv_bfloat16 gWc_hi   [CCH * D_MOD],   gWc_lo   [CCH * D_MOD];

// ---------------------------------------------------------------------------
// base-target-legal PTX helpers (sm_80+)
// ---------------------------------------------------------------------------
__device__ __forceinline__ uint32_t smem_u32(const void* p) {
    uint32_t a;
    asm("{ .reg .u64 t; cvta.to.shared.u64 t, %1; cvt.u32.u64 %0, t; }"
        : "=r"(a) : "l"(p));
    return a;
}
__device__ __forceinline__ void ldsm_x4(uint32_t* r, uint32_t addr) {
    asm volatile("ldmatrix.sync.aligned.m8n8.x4.shared.b16 {%0,%1,%2,%3}, [%4];"
        : "=r"(r[0]), "=r"(r[1]), "=r"(r[2]), "=r"(r[3]) : "r"(addr));
}
__device__ __forceinline__ void mma16816(float* c, const uint32_t* a, const uint32_t* b) {
    asm volatile(
        "mma.sync.aligned.m16n8k16.row.col.f32.bf16.bf16.f32 "
        "{%0,%1,%2,%3}, {%4,%5,%6,%7}, {%8,%9}, {%0,%1,%2,%3};"
        : "+f"(c[0]), "+f"(c[1]), "+f"(c[2]), "+f"(c[3])
        : "r"(a[0]), "r"(a[1]), "r"(a[2]), "r"(a[3]), "r"(b[0]), "r"(b[1]));
}
#define CP16(dst, src) \
    asm volatile("cp.async.cg.shared.global [%0], [%1], 16;" \
        :: "r"(dst), "l"(src) : "memory")
#define CP_COMMIT() asm volatile("cp.async.commit_group;" ::: "memory")
#define CP_WAIT0()  asm volatile("cp.async.wait_group 0;" ::: "memory")
#define CP_WAIT1()  asm volatile("cp.async.wait_group 1;" ::: "memory")

// pack 8 floats -> 8 bf16 (hi) and 8 residual bf16 (lo) as uint4 each
__device__ __forceinline__ void pack8(const float* v, uint4& hq, uint4& lq) {
    __nv_bfloat162 hp[4], lp[4];
#pragma unroll
    for (int i = 0; i < 4; i++) {
        __nv_bfloat16 h0 = __float2bfloat16_rn(v[2*i]);
        __nv_bfloat16 h1 = __float2bfloat16_rn(v[2*i+1]);
        hp[i].x = h0; hp[i].y = h1;
        lp[i].x = __float2bfloat16_rn(v[2*i]   - __bfloat162float(h0));
        lp[i].y = __float2bfloat16_rn(v[2*i+1] - __bfloat162float(h1));
    }
    hq = *(uint4*)hp;
    lq = *(uint4*)lp;
}

// ---------------------------------------------------------------------------
// bf16x3 HMMA GEMM (round-11 validated). BM=128, BN=128, BK=32; 512 threads,
// 16 warps (4m x 4n), warp tile 32x32. 3-stage cp.async, 1 sync/chunk.
// ---------------------------------------------------------------------------
#define RS 40
#define SM_AH 0
#define SM_AL 10240
#define SM_BH 20480
#define SM_BL 30720
#define SM_BUF 40960
#define GSM_TOTAL (3 * SM_BUF)   // 122880

__global__ __launch_bounds__(512) void gemm_mma(
    const __nv_bfloat16* __restrict__ Ahi, const __nv_bfloat16* __restrict__ Alo,
    const __nv_bfloat16* __restrict__ Bhi, const __nv_bfloat16* __restrict__ Blo,
    float* __restrict__ C, int M, int N, int K,
    const float* __restrict__ bias, const float* __restrict__ resid, int relu,
    __nv_bfloat16* __restrict__ Ohi, __nv_bfloat16* __restrict__ Olo,
    float* __restrict__ sai)
{
    extern __shared__ char sm[];
    const uint32_t smb = smem_u32(sm);
    const int tid = threadIdx.x;
    const int lane = tid & 31;
    const int wid = tid >> 5;
    const int warpm = wid & 3;
    const int warpn = wid >> 2;
    const int m0 = blockIdx.y * 128;
    const int n0 = blockIdx.x * 128;

    const int row = tid >> 2;
    const int seg = tid & 3;
    const uint32_t ld_sm_off = (uint32_t)row * (RS * 2) + seg * 16;
    const __nv_bfloat16* pAh = Ahi + (size_t)(m0 + row) * K + seg * 8;
    const __nv_bfloat16* pAl = Alo + (size_t)(m0 + row) * K + seg * 8;
    const __nv_bfloat16* pBh = Bhi + (size_t)(n0 + row) * K + seg * 8;
    const __nv_bfloat16* pBl = Blo + (size_t)(n0 + row) * K + seg * 8;

    const int nch = K >> 5;

#pragma unroll
    for (int pt = 0; pt < 2; pt++) {
        const uint32_t stg = (uint32_t)pt * SM_BUF;
        const size_t kc = (size_t)pt * 32;
        CP16(smb + stg + SM_AH + ld_sm_off, pAh + kc);
        CP16(smb + stg + SM_AL + ld_sm_off, pAl + kc);
        CP16(smb + stg + SM_BH + ld_sm_off, pBh + kc);
        CP16(smb + stg + SM_BL + ld_sm_off, pBl + kc);
        CP_COMMIT();
    }

    float acc[2][4][4];
#pragma unroll
    for (int im = 0; im < 2; im++)
#pragma unroll
        for (int in = 0; in < 4; in++)
#pragma unroll
            for (int r = 0; r < 4; r++) acc[im][in][r] = 0.f;

    const uint32_t a_ld_row = (uint32_t)(warpm * 32 + (lane & 15));
    const uint32_t a_ld_k8  = (uint32_t)((lane >> 4) * 8);
    const uint32_t b_ld_row = (uint32_t)(warpn * 32 + ((lane >> 4) & 1) * 8 + (lane & 7));
    const uint32_t b_ld_k8  = (uint32_t)(((lane >> 3) & 1) * 8);

    int sc = 0;
    for (int t = 0; t < nch; t++) {
        if (t + 1 < nch) { CP_WAIT1(); } else { CP_WAIT0(); }
        __syncthreads();

        if (t + 2 < nch) {
            const int si = (sc >= 1) ? sc - 1 : 2;
            const uint32_t stg = (uint32_t)si * SM_BUF;
            const size_t kc = (size_t)(t + 2) * 32;
            CP16(smb + stg + SM_AH + ld_sm_off, pAh + kc);
            CP16(smb + stg + SM_AL + ld_sm_off, pAl + kc);
            CP16(smb + stg + SM_BH + ld_sm_off, pBh + kc);
            CP16(smb + stg + SM_BL + ld_sm_off, pBl + kc);
            CP_COMMIT();
        }

        const uint32_t cur = (uint32_t)sc * SM_BUF;
#pragma unroll
        for (int ks = 0; ks < 2; ks++) {
            uint32_t ah[2][4], al[2][4], bh[4][2], bl[4][2];
#pragma unroll
            for (int im = 0; im < 2; im++) {
                const uint32_t ao = cur +
                    ((a_ld_row + im * 16) * RS + ks * 16 + a_ld_k8) * 2;
                ldsm_x4(ah[im], smb + SM_AH + ao);
                ldsm_x4(al[im], smb + SM_AL + ao);
            }
#pragma unroll
            for (int p = 0; p < 2; p++) {
                const uint32_t bo = cur +
                    ((b_ld_row + p * 16) * RS + ks * 16 + b_ld_k8) * 2;
                uint32_t r[4];
                ldsm_x4(r, smb + SM_BH + bo);
                bh[2*p][0] = r[0]; bh[2*p][1] = r[1];
                bh[2*p+1][0] = r[2]; bh[2*p+1][1] = r[3];
                ldsm_x4(r, smb + SM_BL + bo);
                bl[2*p][0] = r[0]; bl[2*p][1] = r[1];
                bl[2*p+1][0] = r[2]; bl[2*p+1][1] = r[3];
            }
#pragma unroll
            for (int im = 0; im < 2; im++)
#pragma unroll
                for (int in = 0; in < 4; in++) {
                    mma16816(acc[im][in], ah[im], bh[in]);
                    mma16816(acc[im][in], ah[im], bl[in]);
                    mma16816(acc[im][in], al[im], bh[in]);
                }
        }
        sc = (sc >= 2) ? 0 : sc + 1;
    }

    // ---- epilogue ----
#pragma unroll
    for (int im = 0; im < 2; im++) {
#pragma unroll
        for (int in = 0; in < 4; in++) {
            const int mrow = m0 + warpm * 32 + im * 16 + (lane >> 2);
            const int ncol = n0 + warpn * 32 + in * 8 + (lane & 3) * 2;
#pragma unroll
            for (int r = 0; r < 2; r++) {
                const int m = mrow + r * 8;
                float v0 = acc[im][in][r * 2 + 0];
                float v1 = acc[im][in][r * 2 + 1];
                if (bias)  { v0 += bias[ncol]; v1 += bias[ncol + 1]; }
                if (relu)  { v0 = fmaxf(v0, 0.f); v1 = fmaxf(v1, 0.f); }
                if (resid) {
                    const float* rp = resid + (size_t)m * N + ncol;
                    v0 += rp[0]; v1 += rp[1];
                }
                if (C) {
                    float2 f2; f2.x = v0; f2.y = v1;
                    *(float2*)(C + (size_t)m * N + ncol) = f2;
                }
                if (Ohi) {
                    __nv_bfloat16 h0 = __float2bfloat16_rn(v0);
                    __nv_bfloat16 h1 = __float2bfloat16_rn(v1);
                    __nv_bfloat162 hv; hv.x = h0; hv.y = h1;
                    __nv_bfloat162 lv;
                    lv.x = __float2bfloat16_rn(v0 - __bfloat162float(h0));
                    lv.y = __float2bfloat16_rn(v1 - __bfloat162float(h1));
                    *(__nv_bfloat162*)(Ohi + (size_t)m * N + ncol) = hv;
                    *(__nv_bfloat162*)(Olo + (size_t)m * N + ncol) = lv;
                }
                if (sai) {
                    const int ba = m >> 10, p = m & 1023;
                    const int b_ = ba / AA, a_ = ba - b_ * AA;
                    sai[((size_t)(b_ * CCH + ncol)     * AA + a_) * PIX + p] = v0;
                    sai[((size_t)(b_ * CCH + ncol + 1) * AA + a_) * PIX + p] = v1;
                }
            }
        }
    }
}

// ---------------------------------------------------------------------------
// weight transpose + split kernels
// ---------------------------------------------------------------------------
__global__ void wsplit_kernel(const float* __restrict__ W, int K, int N,
                              __nv_bfloat16* __restrict__ oh,
                              __nv_bfloat16* __restrict__ ol)
{
    const int idx = blockIdx.x * 256 + threadIdx.x;
    if (idx >= K * N) return;
    const int k = idx / N, n = idx - k * N;
    const float v = W[idx];
    const __nv_bfloat16 h = __float2bfloat16_rn(v);
    oh[(size_t)n * K + k] = h;
    ol[(size_t)n * K + k] = __float2bfloat16_rn(v - __bfloat162float(h));
}

__global__ void wsplit_mlp(const float* __restrict__ W,
                           __nv_bfloat16* __restrict__ oh,
                           __nv_bfloat16* __restrict__ ol)
{
    const int idx = blockIdx.x * 256 + threadIdx.x;
    if (idx >= KIN * D_MOD) return;
    const int kk = idx / D_MOD, n = idx - kk * D_MOD;
    const int c = kk / 9, tap = kk - c * 9;
    const int kp = tap * 128 + c;
    const float v = W[idx];
    const __nv_bfloat16 h = __float2bfloat16_rn(v);
    oh[(size_t)n * KIN + kp] = h;
    ol[(size_t)n * KIN + kp] = __float2bfloat16_rn(v - __bfloat162float(h));
}

// vectorized elementwise split: 8 elems/thread, uint4 packed outputs
__global__ void split_kernel(const float* __restrict__ X, size_t n,
                             __nv_bfloat16* __restrict__ oh,
                             __nv_bfloat16* __restrict__ ol)
{
    const size_t i = ((size_t)blockIdx.x * 256 + threadIdx.x) * 8;
    if (i >= n) return;
    float v[8];
    *(float4*)(v)     = *(const float4*)(X + i);
    *(float4*)(v + 4) = *(const float4*)(X + i + 4);
    uint4 hq, lq;
    pack8(v, hq, lq);
    *(uint4*)(oh + i) = hq;
    *(uint4*)(ol + i) = lq;
}

// ---------------------------------------------------------------------------
// im2col (coalesced, round-14 validated): A[m = ba*1024+p][k = tap*128+c].
// ---------------------------------------------------------------------------
__global__ __launch_bounds__(256) void im2col2(
    const float* __restrict__ src,
    __nv_bfloat16* __restrict__ Ahi, __nv_bfloat16* __restrict__ Alo)
{
    __shared__ float xs[32 * 321];
    const int tid = threadIdx.x;
    const int i0 = blockIdx.x * 8;
    const int c0 = blockIdx.y * 32;
    const int ba = blockIdx.z;
    const int b_ = ba / AA, a_ = ba - b_ * AA;

    for (int l = tid; l < 10240; l += 256) {
        const int c = l / 320;
        const int rem = l - c * 320;
        const int r = rem >> 5, col = rem & 31;
        const int ii = i0 - 1 + r;
        float v = 0.f;
        if (ii >= 0 && ii < 32)
            v = src[(((size_t)(b_ * CCH + c0 + c)) * AA + a_) * PIX + ii * 32 + col];
        xs[c * 321 + rem] = v;
    }
    __syncthreads();

    const int w = tid >> 5, lane = tid & 31;
    const int i = i0 + w;
    const float* xrow = xs + lane * 321;
    for (int j = 0; j < 32; j++) {
        const size_t m = (size_t)ba * PIX + i * 32 + j;
        const size_t mbase = m * KIN + c0 + lane;
#pragma unroll
        for (int tap = 0; tap < 9; tap++) {
            const int di = tap / 3, dj = tap - di * 3 - 1;
            const int jj = j + dj;
            float v = 0.f;
            if (jj >= 0 && jj < 32) v = xrow[(w + di) * 32 + jj];
            const __nv_bfloat16 h = __float2bfloat16_rn(v);
            Ahi[mbase + (size_t)tap * 128] = h;
            Alo[mbase + (size_t)tap * 128] =
                __float2bfloat16_rn(v - __bfloat162float(h));
        }
    }
}

// ---------------------------------------------------------------------------
// LayerNorm v2: warp-per-row (8 rows/CTA), float4 loads, uint4 packed stores.
// ---------------------------------------------------------------------------
__global__ __launch_bounds__(256) void ln_kernel(
    const float* __restrict__ X, const float* __restrict__ addsrc,
    const float* __restrict__ g, const float* __restrict__ b,
    __nv_bfloat16* __restrict__ oh, __nv_bfloat16* __restrict__ ol)
{
    const int w = threadIdx.x >> 5, lane = threadIdx.x & 31;
    const size_t row = (size_t)blockIdx.x * 8 + w;
    const size_t base = row * D_MOD + lane * 8;

    float v[8];
    *(float4*)(v)     = *(const float4*)(X + base);
    *(float4*)(v + 4) = *(const float4*)(X + base + 4);
    if (addsrc) {
        float a[8];
        *(float4*)(a)     = *(const float4*)(addsrc + base);
        *(float4*)(a + 4) = *(const float4*)(addsrc + base + 4);
#pragma unroll
        for (int i = 0; i < 8; i++) v[i] += a[i];
    }

    float s = 0.f;
#pragma unroll
    for (int i = 0; i < 8; i++) s += v[i];
#pragma unroll
    for (int o = 16; o; o >>= 1) s += __shfl_xor_sync(0xffffffffu, s, o);
    const float mean = s * (1.f / 256.f);

    float q = 0.f;
#pragma unroll
    for (int i = 0; i < 8; i++) {
        v[i] -= mean;
        q += v[i] * v[i];
    }
#pragma unroll
    for (int o = 16; o; o >>= 1) q += __shfl_xor_sync(0xffffffffu, q, o);
    const float rstd = rsqrtf(q * (1.f / 256.f) + 1e-5f);

    float gv[8], bv[8];
    *(float4*)(gv)     = *(const float4*)(g + lane * 8);
    *(float4*)(gv + 4) = *(const float4*)(g + lane * 8 + 4);
    *(float4*)(bv)     = *(const float4*)(b + lane * 8);
    *(float4*)(bv + 4) = *(const float4*)(b + lane * 8 + 4);

    float r[8];
#pragma unroll
    for (int i = 0; i < 8; i++) r[i] = v[i] * rstd * gv[i] + bv[i];

    uint4 hq, lq;
    pack8(r, hq, lq);
    *(uint4*)(oh + base) = hq;
    *(uint4*)(ol + base) = lq;
}

// ---------------------------------------------------------------------------
// Fused attention v3 — 4-query batching (validated round 11).
// ---------------------------------------------------------------------------
#define KTP 101
#define TAILPAD 64
#define ATT_SMEM_FLOATS (256 * KTP + 25600 + 3200 + 3200 + TAILPAD)
#define ATT_SMEM_BYTES  (ATT_SMEM_FLOATS * 4)

__global__ __launch_bounds__(256) void attn_kernel(
    const float* __restrict__ qkv,
    __nv_bfloat16* __restrict__ outh, __nv_bfloat16* __restrict__ outl,
    const float* __restrict__ Wl, const float* __restrict__ bl,
    const float* __restrict__ Ww, const float* __restrict__ bw,
    const float* __restrict__ lamb)
{
    extern __shared__ float smf[];
    float* Kt   = smf;
    float* Vs   = Kt + 256 * KTP;
    float* sraw = Vs + 25600;
    float* satt = sraw + 3200;

    const int tid = threadIdx.x;
    const int g = tid >> 5, lane = tid & 31;
    const int bq = blockIdx.x;
    const float scale = 0.17677669529663687f;

    float wl[8], ww[8];
#pragma unroll
    for (int h = 0; h < 8; h++) { wl[h] = Wl[g * 8 + h]; ww[h] = Ww[g * 8 + h]; }
    const float blg = bl[g], bwg = bw[g];
    const float lam = 1.f + lamb[g];

    for (int idx = tid; idx < 25600; idx += 256) {
        const int m = idx >> 8, cc = idx & 255;
        const size_t rowb = ((size_t)m * PIX + bq) * QKV_N;
        Kt[cc * KTP + m] = qkv[rowb + 256 + cc];
        Vs[idx]          = qkv[rowb + 512 + cc];
    }
    __syncthreads();

    for (int n = 0; n < BA; n += 4) {
        float qr[4];
#pragma unroll
        for (int q = 0; q < 4; q++)
            qr[q] = qkv[((size_t)(n + q) * PIX + bq) * QKV_N + tid] * scale;

        float a[4][4];
#pragma unroll
        for (int q = 0; q < 4; q++)
#pragma unroll
            for (int r = 0; r < 4; r++) a[q][r] = 0.f;
        const float* kb = Kt + (g * 32) * KTP;
#pragma unroll
        for (int dd = 0; dd < 32; dd++) {
            float qd[4];
#pragma unroll
            for (int q = 0; q < 4; q++)
                qd[q] = __shfl_sync(0xffffffffu, qr[q], dd);
            const float* kr = kb + dd * KTP;
            const float k0 = kr[lane];
            const float k1 = kr[32 + lane];
            const float k2 = kr[64 + lane];
            const float k3 = kr[96 + lane];
#pragma unroll
            for (int q = 0; q < 4; q++) {
                a[q][0] += qd[q] * k0;
                a[q][1] += qd[q] * k1;
                a[q][2] += qd[q] * k2;
                a[q][3] += qd[q] * k3;
            }
        }
#pragma unroll
        for (int q = 0; q < 4; q++) {
            float* srq = sraw + q * 800 + g * 100;
            srq[lane]      = a[q][0];
            srq[32 + lane] = a[q][1];
            srq[64 + lane] = a[q][2];
            if (lane < 4) srq[96 + lane] = a[q][3];
        }
        __syncthreads();

#pragma unroll
        for (int q = 0; q < 4; q++) {
            float s0 = blg, s1 = blg, s2 = blg, s3 = blg;
#pragma unroll
            for (int h = 0; h < 8; h++) {
                const float* sr = sraw + q * 800 + h * 100;
                const float w = wl[h];
                s0 += w * sr[lane];
                s1 += w * sr[32 + lane];
                s2 += w * sr[64 + lane];
                s3 += w * sr[96 + lane];
            }
            if (lane >= 4) s3 = -1e30f;
            float mx = fmaxf(fmaxf(s0, s1), fmaxf(s2, s3));
#pragma unroll
            for (int o = 16; o; o >>= 1) mx = fmaxf(mx, __shfl_xor_sync(0xffffffffu, mx, o));
            float e0 = __expf(s0 - mx);
            float e1 = __expf(s1 - mx);
            float e2 = __expf(s2 - mx);
            float e3 = (lane < 4) ? __expf(s3 - mx) : 0.f;
            float sum = e0 + e1 + e2 + e3;
#pragma unroll
            for (int o = 16; o; o >>= 1) sum += __shfl_xor_sync(0xffffffffu, sum, o);
            const float inv = 1.f / sum;
            float* saq = satt + q * 800 + g * 100;
            saq[lane]      = e0 * inv;
            saq[32 + lane] = e1 * inv;
            saq[64 + lane] = e2 * inv;
            if (lane < 4) saq[96 + lane] = e3 * inv;
        }
        __syncthreads();

        float w4[4][4];
#pragma unroll
        for (int q = 0; q < 4; q++) {
            float w0 = bwg, w1 = bwg, w2 = bwg, w3 = bwg;
#pragma unroll
            for (int h = 0; h < 8; h++) {
                const float* sa = satt + q * 800 + h * 100;
                const float w = ww[h];
                w0 += w * sa[lane];
                w1 += w * sa[32 + lane];
                w2 += w * sa[64 + lane];
                w3 += w * sa[96 + lane];
            }
            w4[q][0] = 0.01f + (w0 - 0.01f) * lam;
            w4[q][1] = 0.01f + (w1 - 0.01f) * lam;
            w4[q][2] = 0.01f + (w2 - 0.01f) * lam;
            w4[q][3] = 0.01f + (w3 - 0.01f) * lam;
        }

        float o4[4] = {0.f, 0.f, 0.f, 0.f};
        const float* vb = Vs + g * 32 + lane;
#pragma unroll 4
        for (int sl = 0; sl < 32; sl++) {
            const float v0 = vb[sl * 256];
            const float v1 = vb[(32 + sl) * 256];
            const float v2 = vb[(64 + sl) * 256];
#pragma unroll
            for (int q = 0; q < 4; q++) {
                o4[q] += __shfl_sync(0xffffffffu, w4[q][0], sl) * v0;
                o4[q] += __shfl_sync(0xffffffffu, w4[q][1], sl) * v1;
                o4[q] += __shfl_sync(0xffffffffu, w4[q][2], sl) * v2;
            }
        }
#pragma unroll
        for (int sl = 0; sl < 4; sl++) {
            const float v3 = vb[(96 + sl) * 256];
#pragma unroll
            for (int q = 0; q < 4; q++)
                o4[q] += __shfl_sync(0xffffffffu, w4[q][3], sl) * v3;
        }
#pragma unroll
        for (int q = 0; q < 4; q++) {
            const size_t oi = ((size_t)(n + q) * PIX + bq) * D_MOD + g * 32 + lane;
            const __nv_bfloat16 h = __float2bfloat16_rn(o4[q]);
            outh[oi] = h;
            outl[oi] = __float2bfloat16_rn(o4[q] - __bfloat162float(h));
        }
    }
}

// ---------------------------------------------------------------------------
extern "C" void kernel_launch(void* const* d_in, const int* in_sizes, int n_in,
                              void* d_out, int out_size)
{
    const float* buffer  = (const float*)d_in[0];
    const float* spa_pos = (const float*)d_in[1];
    const float* W_mlp   = (const float*)d_in[2];
    const float* g1      = (const float*)d_in[3];
    const float* b1      = (const float*)d_in[4];
    const float* Wqkv    = (const float*)d_in[5];
    const float* Wproj   = (const float*)d_in[6];
    const float* bproj   = (const float*)d_in[7];
    const float* Wl      = (const float*)d_in[8];
    const float* bl      = (const float*)d_in[9];
    const float* Ww      = (const float*)d_in[10];
    const float* bw      = (const float*)d_in[11];
    const float* lamb    = (const float*)d_in[12];
    const float* g2      = (const float*)d_in[13];
    const float* b2      = (const float*)d_in[14];
    const float* W1      = (const float*)d_in[15];
    const float* W2      = (const float*)d_in[16];
    const float* Wconv   = (const float*)d_in[17];
    float* out = (float*)d_out;

    float *T, *PE, *QKV, *S2;
    cudaGetSymbolAddress((void**)&T,   g_T);
    cudaGetSymbolAddress((void**)&PE,  g_PE);
    cudaGetSymbolAddress((void**)&QKV, g_QKV);
    cudaGetSymbolAddress((void**)&S2,  g_S2);

    __nv_bfloat16 *Ah, *Al, *Xh, *Xl, *AOh, *AOl, *Yh, *Yl, *Fh, *Fl;
    __nv_bfloat16 *Wmh, *Wml, *Wqh, *Wql, *Wph, *Wpl, *W1h, *W1l, *W2h, *W2l, *Wch, *Wcl;
    cudaGetSymbolAddress((void**)&Ah,  gA_hi);   cudaGetSymbolAddress((void**)&Al,  gA_lo);
    cudaGetSymbolAddress((void**)&Xh,  gX_hi);   cudaGetSymbolAddress((void**)&Xl,  gX_lo);
    cudaGetSymbolAddress((void**)&AOh, gAO_hi);  cudaGetSymbolAddress((void**)&AOl, gAO_lo);
    cudaGetSymbolAddress((void**)&Yh,  gY_hi);   cudaGetSymbolAddress((void**)&Yl,  gY_lo);
    cudaGetSymbolAddress((void**)&Fh,  gF_hi);   cudaGetSymbolAddress((void**)&Fl,  gF_lo);
    cudaGetSymbolAddress((void**)&Wmh, gWmlp_hi);  cudaGetSymbolAddress((void**)&Wml, gWmlp_lo);
    cudaGetSymbolAddress((void**)&Wqh, gWqkv_hi);  cudaGetSymbolAddress((void**)&Wql, gWqkv_lo);
    cudaGetSymbolAddress((void**)&Wph, gWproj_hi); cudaGetSymbolAddress((void**)&Wpl, gWproj_lo);
    cudaGetSymbolAddress((void**)&W1h, gW1_hi);    cudaGetSymbolAddress((void**)&W1l, gW1_lo);
    cudaGetSymbolAddress((void**)&W2h, gW2_hi);    cudaGetSymbolAddress((void**)&W2l, gW2_lo);
    cudaGetSymbolAddress((void**)&Wch, gWc_hi);    cudaGetSymbolAddress((void**)&Wcl, gWc_lo);

    cudaFuncSetAttribute(attn_kernel, cudaFuncAttributeMaxDynamicSharedMemorySize,
                         ATT_SMEM_BYTES);
    cudaFuncSetAttribute(gemm_mma, cudaFuncAttributeMaxDynamicSharedMemorySize,
                         GSM_TOTAL);

    // App launch #4 = ncu capture target (conv GEMM).
    im2col2<<<dim3(4, 4, BA), 256>>>(buffer, Ah, Al);
    wsplit_mlp<<<(KIN * D_MOD + 255) / 256, 256>>>(W_mlp, Wmh, Wml);
    wsplit_kernel<<<(D_MOD * QKV_N + 255) / 256, 256>>>(Wqkv, D_MOD, QKV_N, Wqh, Wql);
    gemm_mma<<<dim3(D_MOD / 128, TOK_M / 128), 512, GSM_TOTAL>>>(
        Ah, Al, Wmh, Wml, T, TOK_M, D_MOD, KIN,
        nullptr, nullptr, 0, nullptr, nullptr, nullptr);
    im2col2<<<dim3(4, 4, BA), 256>>>(spa_pos, Ah, Al);
    gemm_mma<<<dim3(D_MOD / 128, TOK_M / 128), 512, GSM_TOTAL>>>(
        Ah, Al, Wmh, Wml, PE, TOK_M, D_MOD, KIN,
        nullptr, nullptr, 0, nullptr, nullptr, nullptr);
    wsplit_kernel<<<(D_MOD * D_MOD + 255) / 256, 256>>>(Wproj, D_MOD, D_MOD, Wph, Wpl);
    wsplit_kernel<<<(D_MOD * D_FF + 255) / 256, 256>>>(W1, D_MOD, D_FF, W1h, W1l);
    wsplit_kernel<<<(D_FF * D_MOD + 255) / 256, 256>>>(W2, D_FF, D_MOD, W2h, W2l);
    split_kernel<<<(CCH * D_MOD / 8 + 255) / 256, 256>>>(
        Wconv, (size_t)CCH * D_MOD, Wch, Wcl);

    ln_kernel<<<TOK_M / 8, 256>>>(T, PE, g1, b1, Xh, Xl);

    gemm_mma<<<dim3(QKV_N / 128, TOK_M / 128), 512, GSM_TOTAL>>>(
        Xh, Xl, Wqh, Wql, QKV, TOK_M, QKV_N, D_MOD,
        nullptr, nullptr, 0, nullptr, nullptr, nullptr);

    attn_kernel<<<PIX, 256, ATT_SMEM_BYTES>>>(QKV, AOh, AOl, Wl, bl, Ww, bw, lamb);

    gemm_mma<<<dim3(D_MOD / 128, TOK_M / 128), 512, GSM_TOTAL>>>(
        AOh, AOl, Wph, Wpl, S2, TOK_M, D_MOD, D_MOD,
        bproj, T, 0, nullptr, nullptr, nullptr);

    ln_kernel<<<TOK_M / 8, 256>>>(S2, nullptr, g2, b2, Yh, Yl);

    gemm_mma<<<dim3(D_FF / 128, TOK_M / 128), 512, GSM_TOTAL>>>(
        Yh, Yl, W1h, W1l, nullptr, TOK_M, D_FF, D_MOD,
        nullptr, nullptr, 1, Fh, Fl, nullptr);
    gemm_mma<<<dim3(D_MOD / 128, TOK_M / 128), 512, GSM_TOTAL>>>(
        Fh, Fl, W2h, W2l, nullptr, TOK_M, D_MOD, D_FF,
        nullptr, S2, 0, Xh, Xl, nullptr);

    gemm_mma<<<dim3(CCH / 128, TOK_M / 128), 512, GSM_TOTAL>>>(
        Xh, Xl, Wch, Wcl, nullptr, TOK_M, CCH, D_MOD,
        nullptr, nullptr, 0, nullptr, nullptr, out);
}